// round 15
// baseline (speedup 1.0000x reference)
#include <cuda_runtime.h>
#include <cuda_bf16.h>

// InnerProduct_541165879452
// lp[r,p] = sum_f w[p,f]^2 * sum_e x[r,f,e]^2
// x: [32768, 64, 16] f32 (row = 4 KB), w: [10,64] f32, out: [R,10] f32.
//
// R13 (best, 27.4us / 5.37 TB/s) with the same L1-wavefront lever pulled
// harder:
//  - 4 rows per warp (weights loaded once -> 10 wf/row amortized, was 20)
//  - single coalesced 10-lane STG.32 per row (1 wf, was ten sparse STG.64)
// Per-row compute body unchanged.

#define F_DIM 64
#define P_DIM 10
#define ROW_FLOATS 1024
#define WARPS_PER_BLOCK 8
#define ROWS_PER_WARP 4

__global__ __launch_bounds__(32 * WARPS_PER_BLOCK, 5)
void ip_kernel(const float* __restrict__ x,
               const float* __restrict__ w,
               float* __restrict__ out,
               int R)
{
    const int wid  = threadIdx.x >> 5;
    const int lane = threadIdx.x & 31;
    const int row0 = (blockIdx.x * WARPS_PER_BLOCK + wid) * ROWS_PER_WARP;
    if (row0 >= R) return;

    const int c = lane >> 2;   // 0..7 : f-slot within an i-group
    const int q = lane & 3;    // 0..3 : which i-pair this lane owns
    const int f_a = 16 * q + c;
    const int f_b = f_a + 8;

    // Squared weights: loaded ONCE per warp, reused for all 4 rows.
    float wa[P_DIM], wb[P_DIM];
#pragma unroll
    for (int p = 0; p < P_DIM; p++) {
        float va = __ldg(&w[p * F_DIM + f_a]);
        float vb = __ldg(&w[p * F_DIM + f_b]);
        wa[p] = va * va;
        wb[p] = vb * vb;
    }

    // Store lane mapping: lanes 0..4 store p0..4, lanes 16..20 store p5..9.
    const int hl  = lane & 15;            // index within 16-lane half
    const bool st = hl < 5;               // this lane stores one output
    const int pofs = (lane & 16) ? 5 : 0; // which half of p-range

#pragma unroll
    for (int rr = 0; rr < ROWS_PER_WARP; rr++) {
        const int row = row0 + rr;
        if (row >= R) break;

        const float4* __restrict__ xr =
            reinterpret_cast<const float4*>(x + (size_t)row * ROW_FLOATS);

        // 8 coalesced LDG.128: lane l reads float4 #(i*32 + l).
        float4 v[8];
#pragma unroll
        for (int i = 0; i < 8; i++) v[i] = xr[i * 32 + lane];

        // Per-quarter sum of squares.
        float s[8];
#pragma unroll
        for (int i = 0; i < 8; i++) {
            float t = v[i].x * v[i].x;
            t = fmaf(v[i].y, v[i].y, t);
            t = fmaf(v[i].z, v[i].z, t);
            s[i] = fmaf(v[i].w, v[i].w, t);
        }

        // Quad reduce: lanes {4c..4c+3} share f for every i.
#pragma unroll
        for (int i = 0; i < 8; i++) {
            s[i] += __shfl_xor_sync(0xffffffffu, s[i], 1);
            s[i] += __shfl_xor_sync(0xffffffffu, s[i], 2);
        }

        // Static select of this lane's two owned xsq values (f_a, f_b).
        float xa = (q == 0) ? s[0] : (q == 1) ? s[2] : (q == 2) ? s[4] : s[6];
        float xb = (q == 0) ? s[1] : (q == 1) ? s[3] : (q == 2) ? s[5] : s[7];

        float acc[P_DIM];
#pragma unroll
        for (int p = 0; p < P_DIM; p++)
            acc[p] = fmaf(xa, wa[p], xb * wb[p]);

        // Split butterfly: xor16 on all 10, then halves carry 5 each.
#pragma unroll
        for (int p = 0; p < P_DIM; p++)
            acc[p] += __shfl_xor_sync(0xffffffffu, acc[p], 16);

        const bool hi = (lane & 16) != 0;
        float a2[5];
#pragma unroll
        for (int j = 0; j < 5; j++)
            a2[j] = hi ? acc[j + 5] : acc[j];

#pragma unroll
        for (int off = 8; off >= 1; off >>= 1) {
#pragma unroll
            for (int j = 0; j < 5; j++)
                a2[j] += __shfl_xor_sync(0xffffffffu, a2[j], off);
        }

        // One coalesced store: 10 active lanes write 40 contiguous bytes.
        // (static select -- no dynamic register indexing)
        float val = (hl == 0) ? a2[0]
                  : (hl == 1) ? a2[1]
                  : (hl == 2) ? a2[2]
                  : (hl == 3) ? a2[3]
                  :             a2[4];
        if (st)
            out[(size_t)row * P_DIM + pofs + hl] = val;
    }
}

extern "C" void kernel_launch(void* const* d_in, const int* in_sizes, int n_in,
                              void* d_out, int out_size)
{
    const float* x = (const float*)d_in[0];
    const float* w = (const float*)d_in[1];
    float* out = (float*)d_out;

    const int R = in_sizes[0] / ROW_FLOATS;   // 32768
    const int rows_per_block = WARPS_PER_BLOCK * ROWS_PER_WARP;   // 32
    const int blocks = (R + rows_per_block - 1) / rows_per_block; // 1024

    ip_kernel<<<blocks, 32 * WARPS_PER_BLOCK>>>(x, w, out, R);
}

// round 16
// speedup vs baseline: 1.0655x; 1.0655x over previous
#include <cuda_runtime.h>
#include <cuda_bf16.h>

// InnerProduct_541165879452
// lp[r,p] = sum_f w[p,f]^2 * sum_e x[r,f,e]^2
// x: [32768, 64, 16] f32 (row = 4 KB), w: [10,64] f32, out: [R,10] f32.
//
// R13 (best: 2 rows/warp, kernel 25.8us / 5.37 TB/s) + ONLY the coalesced
// store delta from R15 (one 10-lane STG.32 per row instead of ten sparse
// STG.64), isolating it from the ROWS_PER_WARP=4 change that caused R15's
// regression. Inner bounds predicates dropped (R multiple of 16).

#define F_DIM 64
#define P_DIM 10
#define ROW_FLOATS 1024
#define WARPS_PER_BLOCK 8
#define ROWS_PER_WARP 2

__global__ __launch_bounds__(32 * WARPS_PER_BLOCK, 5)
void ip_kernel(const float* __restrict__ x,
               const float* __restrict__ w,
               float* __restrict__ out,
               int R)
{
    const int wid  = threadIdx.x >> 5;
    const int lane = threadIdx.x & 31;
    const int row0 = (blockIdx.x * WARPS_PER_BLOCK + wid) * ROWS_PER_WARP;
    if (row0 >= R) return;

    const int c = lane >> 2;   // 0..7 : f-slot within an i-group
    const int q = lane & 3;    // 0..3 : which i-pair this lane owns
    const int f_a = 16 * q + c;
    const int f_b = f_a + 8;

    // Squared weights: loaded ONCE per warp, reused for both rows.
    float wa[P_DIM], wb[P_DIM];
#pragma unroll
    for (int p = 0; p < P_DIM; p++) {
        float va = __ldg(&w[p * F_DIM + f_a]);
        float vb = __ldg(&w[p * F_DIM + f_b]);
        wa[p] = va * va;
        wb[p] = vb * vb;
    }

    // Store lane mapping: lanes 0..4 store p0..4, lanes 16..20 store p5..9.
    const int hl   = lane & 15;            // index within 16-lane half
    const bool st  = hl < 5;               // this lane stores one output
    const int pofs = (lane & 16) ? 5 : 0;  // which half of the p-range

#pragma unroll
    for (int rr = 0; rr < ROWS_PER_WARP; rr++) {
        const int row = row0 + rr;

        const float4* __restrict__ xr =
            reinterpret_cast<const float4*>(x + (size_t)row * ROW_FLOATS);

        // 8 coalesced LDG.128: lane l reads float4 #(i*32 + l).
        float4 v[8];
#pragma unroll
        for (int i = 0; i < 8; i++) v[i] = xr[i * 32 + lane];

        // Per-quarter sum of squares.
        float s[8];
#pragma unroll
        for (int i = 0; i < 8; i++) {
            float t = v[i].x * v[i].x;
            t = fmaf(v[i].y, v[i].y, t);
            t = fmaf(v[i].z, v[i].z, t);
            s[i] = fmaf(v[i].w, v[i].w, t);
        }

        // Quad reduce: lanes {4c..4c+3} share f for every i.
#pragma unroll
        for (int i = 0; i < 8; i++) {
            s[i] += __shfl_xor_sync(0xffffffffu, s[i], 1);
            s[i] += __shfl_xor_sync(0xffffffffu, s[i], 2);
        }

        // Static select of this lane's two owned xsq values (f_a, f_b).
        float xa = (q == 0) ? s[0] : (q == 1) ? s[2] : (q == 2) ? s[4] : s[6];
        float xb = (q == 0) ? s[1] : (q == 1) ? s[3] : (q == 2) ? s[5] : s[7];

        float acc[P_DIM];
#pragma unroll
        for (int p = 0; p < P_DIM; p++)
            acc[p] = fmaf(xa, wa[p], xb * wb[p]);

        // Split butterfly: xor16 on all 10, then halves carry 5 each.
#pragma unroll
        for (int p = 0; p < P_DIM; p++)
            acc[p] += __shfl_xor_sync(0xffffffffu, acc[p], 16);

        const bool hi = (lane & 16) != 0;
        float a2[5];
#pragma unroll
        for (int j = 0; j < 5; j++)
            a2[j] = hi ? acc[j + 5] : acc[j];

#pragma unroll
        for (int off = 8; off >= 1; off >>= 1) {
#pragma unroll
            for (int j = 0; j < 5; j++)
                a2[j] += __shfl_xor_sync(0xffffffffu, a2[j], off);
        }

        // One coalesced store: 10 active lanes write 40 contiguous bytes
        // (static select -- no dynamic register indexing).
        float val = (hl == 0) ? a2[0]
                  : (hl == 1) ? a2[1]
                  : (hl == 2) ? a2[2]
                  : (hl == 3) ? a2[3]
                  :             a2[4];
        if (st)
            out[(size_t)row * P_DIM + pofs + hl] = val;
    }
}

extern "C" void kernel_launch(void* const* d_in, const int* in_sizes, int n_in,
                              void* d_out, int out_size)
{
    const float* x = (const float*)d_in[0];
    const float* w = (const float*)d_in[1];
    float* out = (float*)d_out;

    const int R = in_sizes[0] / ROW_FLOATS;   // 32768
    const int rows_per_block = WARPS_PER_BLOCK * ROWS_PER_WARP;   // 16
    const int blocks = (R + rows_per_block - 1) / rows_per_block; // 2048

    ip_kernel<<<blocks, 32 * WARPS_PER_BLOCK>>>(x, w, out, R);
}